// round 3
// baseline (speedup 1.0000x reference)
#include <cuda_runtime.h>
#include <cuda_bf16.h>

#define S_LEN 4096
#define HID   2048
#define QKV_LD 3072
#define WIN_  1024
#define SCALE_F 0.08838834764831845f   // 128^-0.5

static __device__ float g_qkv [S_LEN * QKV_LD];   // [s][ q(16*128) | k(4*128) | v(4*128) ]
static __device__ float g_attn[S_LEN * HID];

// ============================================================================
// GEMM:  C[M,N] = A[M,K] * B[N,K]^T     (both row-major, K contiguous)
// 128x128 block tile, BK=16, 256 threads, 8x8 microtile (split 4+4 pattern)
// Grid: (N/128, M/128)
// ============================================================================
__global__ __launch_bounds__(256)
void gemm_abt(const float* __restrict__ A, int lda,
              const float* __restrict__ B, int ldb,
              float* __restrict__ C, int ldc,
              int K)
{
    __shared__ float As[16][132];
    __shared__ float Bs[16][132];

    const int bm = blockIdx.y * 128;
    const int bn = blockIdx.x * 128;
    const int tid = threadIdx.x;
    const int ty = tid >> 4;      // 0..15
    const int tx = tid & 15;      // 0..15

    float acc[8][8];
    #pragma unroll
    for (int i = 0; i < 8; i++)
        #pragma unroll
        for (int j = 0; j < 8; j++) acc[i][j] = 0.f;

    const int lr = tid >> 2;            // 0..63  (load row)
    const int lc = (tid & 3) << 2;      // 0,4,8,12 (load col base)
    const float* Ap = A + (bm + lr) * lda + lc;
    const float* Bp = B + (bn + lr) * ldb + lc;

    for (int k0 = 0; k0 < K; k0 += 16) {
        float4 a0 = *(const float4*)(Ap + k0);
        float4 a1 = *(const float4*)(Ap + 64 * lda + k0);
        float4 b0 = *(const float4*)(Bp + k0);
        float4 b1 = *(const float4*)(Bp + 64 * ldb + k0);
        __syncthreads();
        As[lc + 0][lr] = a0.x; As[lc + 1][lr] = a0.y;
        As[lc + 2][lr] = a0.z; As[lc + 3][lr] = a0.w;
        As[lc + 0][lr + 64] = a1.x; As[lc + 1][lr + 64] = a1.y;
        As[lc + 2][lr + 64] = a1.z; As[lc + 3][lr + 64] = a1.w;
        Bs[lc + 0][lr] = b0.x; Bs[lc + 1][lr] = b0.y;
        Bs[lc + 2][lr] = b0.z; Bs[lc + 3][lr] = b0.w;
        Bs[lc + 0][lr + 64] = b1.x; Bs[lc + 1][lr + 64] = b1.y;
        Bs[lc + 2][lr + 64] = b1.z; Bs[lc + 3][lr + 64] = b1.w;
        __syncthreads();

        #pragma unroll
        for (int kk = 0; kk < 16; kk++) {
            float af[8], bf[8];
            *(float4*)(af)     = *(const float4*)&As[kk][ty * 4];
            *(float4*)(af + 4) = *(const float4*)&As[kk][64 + ty * 4];
            *(float4*)(bf)     = *(const float4*)&Bs[kk][tx * 4];
            *(float4*)(bf + 4) = *(const float4*)&Bs[kk][64 + tx * 4];
            #pragma unroll
            for (int i = 0; i < 8; i++)
                #pragma unroll
                for (int j = 0; j < 8; j++)
                    acc[i][j] += af[i] * bf[j];
        }
    }

    #pragma unroll
    for (int i = 0; i < 8; i++) {
        int r = bm + ((i < 4) ? (ty * 4 + i) : (64 + ty * 4 + (i - 4)));
        float* Cr = C + r * ldc + bn;
        *(float4*)(Cr + tx * 4)      = make_float4(acc[i][0], acc[i][1], acc[i][2], acc[i][3]);
        *(float4*)(Cr + 64 + tx * 4) = make_float4(acc[i][4], acc[i][5], acc[i][6], acc[i][7]);
    }
}

// ============================================================================
// RoPE (in-place on g_qkv): q heads 0..15 and k heads 16..19 are contiguous
// cols [0, 2560). tmp = concat(x[64:], x[:64]) with NO negation.
// ============================================================================
__global__ __launch_bounds__(256)
void rope_kernel(const float* __restrict__ cosb, const float* __restrict__ sinb)
{
    const int s = blockIdx.x;
    const float* cs = cosb + s * 128;
    const float* sn = sinb + s * 128;
    float* row = g_qkv + s * QKV_LD;
    for (int p = threadIdx.x; p < 20 * 64; p += 256) {
        const int head = p >> 6;       // 0..19 (16 q heads then 4 k heads)
        const int d = p & 63;          // 0..63
        float* base = row + head * 128;
        float x0 = base[d];
        float x1 = base[d + 64];
        base[d]      = x0 * cs[d]      + x1 * sn[d];
        base[d + 64] = x1 * cs[d + 64] + x0 * sn[d + 64];
    }
}

// ============================================================================
// Sliding-window flash attention, fp32.
// grid (16 heads, 64 q-blocks of 64), 256 threads.
// BQ=BK=64, HD=128; 4x4 S microtile, 4x8 O microtile per thread.
// ============================================================================
#define QK_PAD 129
#define V_PAD  132
#define P_PAD  65
#define ATTN_SMEM ((64 * QK_PAD * 2 + 64 * V_PAD + 64 * P_PAD) * 4)

__global__ __launch_bounds__(256)
void attn_kernel()
{
    extern __shared__ float smf[];
    float* Qs = smf;                       // 64 x 129
    float* Ks = Qs + 64 * QK_PAD;          // 64 x 129
    float* Vs = Ks + 64 * QK_PAD;          // 64 x 132
    float* Ps = Vs + 64 * V_PAD;           // 64 x 65

    const int h   = blockIdx.x;
    const int q0  = blockIdx.y * 64;
    const int kvh = h >> 2;
    const int tid = threadIdx.x;
    const int ty  = tid >> 4;              // 0..15
    const int tx  = tid & 15;              // 0..15

    // load Q tile (scaled by 1/sqrt(HD))
    for (int idx = tid; idx < 64 * 32; idx += 256) {
        int r = idx >> 5, c = (idx & 31) << 2;
        float4 v = *(const float4*)(g_qkv + (q0 + r) * QKV_LD + h * 128 + c);
        float* q = Qs + r * QK_PAD + c;
        q[0] = v.x * SCALE_F; q[1] = v.y * SCALE_F;
        q[2] = v.z * SCALE_F; q[3] = v.w * SCALE_F;
    }

    float m[4], l[4], acc[4][8];
    #pragma unroll
    for (int a = 0; a < 4; a++) {
        m[a] = -1e30f; l[a] = 0.f;
        #pragma unroll
        for (int c = 0; c < 8; c++) acc[a][c] = 0.f;
    }

    const int kstart = (q0 >= WIN_) ? (q0 - WIN_) : 0;

    for (int k0 = kstart; k0 <= q0; k0 += 64) {
        __syncthreads();   // prior PV done reading Vs
        // load K and V tiles
        for (int idx = tid; idx < 64 * 32; idx += 256) {
            int r = idx >> 5, c = (idx & 31) << 2;
            const float* src = g_qkv + (k0 + r) * QKV_LD + 2048 + kvh * 128 + c;
            float4 kv = *(const float4*)src;
            float* kd = Ks + r * QK_PAD + c;
            kd[0] = kv.x; kd[1] = kv.y; kd[2] = kv.z; kd[3] = kv.w;
            *(float4*)(Vs + r * V_PAD + c) = *(const float4*)(src + 512);
        }
        __syncthreads();

        // S = Q * K^T  (4x4 per thread)
        float s[4][4];
        #pragma unroll
        for (int a = 0; a < 4; a++)
            #pragma unroll
            for (int b = 0; b < 4; b++) s[a][b] = 0.f;

        #pragma unroll 4
        for (int d = 0; d < 128; d++) {
            float af[4], bf[4];
            #pragma unroll
            for (int a = 0; a < 4; a++) af[a] = Qs[(ty * 4 + a) * QK_PAD + d];
            #pragma unroll
            for (int b = 0; b < 4; b++) bf[b] = Ks[(tx * 4 + b) * QK_PAD + d];
            #pragma unroll
            for (int a = 0; a < 4; a++)
                #pragma unroll
                for (int b = 0; b < 4; b++)
                    s[a][b] += af[a] * bf[b];
        }

        // mask + online softmax
        #pragma unroll
        for (int a = 0; a < 4; a++) {
            const int i = q0 + ty * 4 + a;
            float rowmax = -1e30f;
            #pragma unroll
            for (int b = 0; b < 4; b++) {
                const int j = k0 + tx * 4 + b;
                const bool ok = (j <= i) && ((i - j) < WIN_);
                s[a][b] = ok ? s[a][b] : -1e30f;
                rowmax = fmaxf(rowmax, s[a][b]);
            }
            #pragma unroll
            for (int off = 8; off > 0; off >>= 1)
                rowmax = fmaxf(rowmax, __shfl_xor_sync(0xffffffffu, rowmax, off));
            const float mnew = fmaxf(m[a], rowmax);
            const float sc = __expf(m[a] - mnew);
            float rs = 0.f;
            #pragma unroll
            for (int b = 0; b < 4; b++) {
                float p = __expf(s[a][b] - mnew);
                Ps[(ty * 4 + a) * P_PAD + tx * 4 + b] = p;
                rs += p;
            }
            #pragma unroll
            for (int off = 8; off > 0; off >>= 1)
                rs += __shfl_xor_sync(0xffffffffu, rs, off);
            l[a] = l[a] * sc + rs;
            m[a] = mnew;
            #pragma unroll
            for (int c = 0; c < 8; c++) acc[a][c] *= sc;
        }
        __syncthreads();

        // O += P * V
        #pragma unroll 4
        for (int j = 0; j < 64; j++) {
            float p[4];
            #pragma unroll
            for (int a = 0; a < 4; a++) p[a] = Ps[(ty * 4 + a) * P_PAD + j];
            float4 v0 = *(const float4*)(Vs + j * V_PAD + tx * 8);
            float4 v1 = *(const float4*)(Vs + j * V_PAD + tx * 8 + 4);
            #pragma unroll
            for (int a = 0; a < 4; a++) {
                acc[a][0] += p[a] * v0.x; acc[a][1] += p[a] * v0.y;
                acc[a][2] += p[a] * v0.z; acc[a][3] += p[a] * v0.w;
                acc[a][4] += p[a] * v1.x; acc[a][5] += p[a] * v1.y;
                acc[a][6] += p[a] * v1.z; acc[a][7] += p[a] * v1.w;
            }
        }
    }

    // epilogue: normalize, write [s, h*128 + d]
    #pragma unroll
    for (int a = 0; a < 4; a++) {
        const float inv = 1.f / l[a];
        float* dst = g_attn + (q0 + ty * 4 + a) * HID + h * 128 + tx * 8;
        float4 o0 = make_float4(acc[a][0] * inv, acc[a][1] * inv, acc[a][2] * inv, acc[a][3] * inv);
        float4 o1 = make_float4(acc[a][4] * inv, acc[a][5] * inv, acc[a][6] * inv, acc[a][7] * inv);
        *(float4*)(dst)     = o0;
        *(float4*)(dst + 4) = o1;
    }
}

// ============================================================================
// Launch
// ============================================================================
extern "C" void kernel_launch(void* const* d_in, const int* in_sizes, int n_in,
                              void* d_out, int out_size)
{
    (void)in_sizes; (void)n_in; (void)out_size;
    const float* hidden = (const float*)d_in[0];
    const float* wq = (const float*)d_in[1];
    const float* wk = (const float*)d_in[2];
    const float* wv = (const float*)d_in[3];
    const float* wo = (const float*)d_in[4];
    const float* cosb = (const float*)d_in[5];
    const float* sinb = (const float*)d_in[6];
    float* out = (float*)d_out;

    void *qkvp, *attnp;
    cudaGetSymbolAddress(&qkvp, g_qkv);
    cudaGetSymbolAddress(&attnp, g_attn);
    float* qkv  = (float*)qkvp;
    float* attn = (float*)attnp;

    // QKV projections (C = A * W^T)
    gemm_abt<<<dim3(16, 32), 256>>>(hidden, HID, wq, HID, qkv,        QKV_LD, HID);
    gemm_abt<<<dim3( 4, 32), 256>>>(hidden, HID, wk, HID, qkv + 2048, QKV_LD, HID);
    gemm_abt<<<dim3( 4, 32), 256>>>(hidden, HID, wv, HID, qkv + 2560, QKV_LD, HID);

    // RoPE on q and k
    rope_kernel<<<S_LEN, 256>>>(cosb, sinb);

    // sliding-window attention
    cudaFuncSetAttribute(attn_kernel, cudaFuncAttributeMaxDynamicSharedMemorySize, ATTN_SMEM);
    attn_kernel<<<dim3(16, 64), 256, ATTN_SMEM>>>();

    // output projection
    gemm_abt<<<dim3(16, 32), 256>>>(attn, HID, wo, HID, out, HID, HID);
}

// round 4
// speedup vs baseline: 3.1676x; 3.1676x over previous
#include <cuda_runtime.h>

#define S_LEN 4096
#define HID   2048
#define QKV_LD 3072
#define WIN_  1024
#define SCALE_F 0.08838834764831845f   // 128^-0.5

static __device__ float g_qkv [S_LEN * QKV_LD];   // [s][ q(16*128) | k(4*128) | v(4*128) ]
static __device__ float g_attn[S_LEN * HID];

// ---------------------------------------------------------------------------
// helpers
// ---------------------------------------------------------------------------
__device__ __forceinline__ float to_tf32(float x) {
    unsigned u;
    asm("cvt.rna.tf32.f32 %0, %1;" : "=r"(u) : "f"(x));
    return __uint_as_float(u);
}

// D = A(16x8, row) * B(8x8, col) + D, tf32 in f32 regs
__device__ __forceinline__ void mma_tf32(float* c, const unsigned* a, const unsigned* b) {
    asm volatile(
        "mma.sync.aligned.m16n8k8.row.col.f32.tf32.tf32.f32 "
        "{%0,%1,%2,%3}, {%4,%5,%6,%7}, {%8,%9}, {%0,%1,%2,%3};\n"
        : "+f"(c[0]), "+f"(c[1]), "+f"(c[2]), "+f"(c[3])
        : "r"(a[0]), "r"(a[1]), "r"(a[2]), "r"(a[3]), "r"(b[0]), "r"(b[1]));
}

__device__ __forceinline__ unsigned fu(float x) { return __float_as_uint(x); }

// ===========================================================================
// GEMM:  C[M,N] = A[M,K] * B[N,K]^T   (row-major, K contiguous), tf32 mma
// BM=128, BN=256, BK=32; 256 threads = 8 warps as 2(M) x 4(N); warp tile 64x64
// ===========================================================================
#define GP 36   // smem row pitch (BK=32 + 4) -> conflict-free fragment LDS

__global__ __launch_bounds__(256, 1)
void gemm_tf32(const float* __restrict__ A, int lda,
               const float* __restrict__ B, int ldb,
               float* __restrict__ C, int ldc, int K)
{
    extern __shared__ float sm[];
    float* As = sm;               // [128][GP]
    float* Bs = sm + 128 * GP;    // [256][GP]

    const int bm = blockIdx.y * 128;
    const int bn = blockIdx.x * 256;
    const int tid  = threadIdx.x;
    const int w    = tid >> 5;
    const int lane = tid & 31;
    const int g    = lane >> 2;
    const int qd   = lane & 3;
    const int wm   = (w & 1) * 64;
    const int wn   = (w >> 1) * 64;

    const int lr = tid >> 3;            // 0..31
    const int lc = (tid & 7) * 4;       // 0..28

    float acc[4][8][4];
    #pragma unroll
    for (int mt = 0; mt < 4; mt++)
        #pragma unroll
        for (int nt = 0; nt < 8; nt++)
            #pragma unroll
            for (int e = 0; e < 4; e++) acc[mt][nt][e] = 0.f;

    const float* Ab = A + (long)(bm + lr) * lda + lc;
    const float* Bb = B + (long)(bn + lr) * ldb + lc;

    float4 pa[4], pb[8];
    #pragma unroll
    for (int j = 0; j < 4; j++) pa[j] = *(const float4*)(Ab + (long)32 * j * lda);
    #pragma unroll
    for (int j = 0; j < 8; j++) pb[j] = *(const float4*)(Bb + (long)32 * j * ldb);

    const int niter = K / 32;
    for (int it = 0; it < niter; it++) {
        __syncthreads();
        #pragma unroll
        for (int j = 0; j < 4; j++) {
            float* d = As + (32 * j + lr) * GP + lc;
            d[0] = to_tf32(pa[j].x); d[1] = to_tf32(pa[j].y);
            d[2] = to_tf32(pa[j].z); d[3] = to_tf32(pa[j].w);
        }
        #pragma unroll
        for (int j = 0; j < 8; j++) {
            float* d = Bs + (32 * j + lr) * GP + lc;
            d[0] = to_tf32(pb[j].x); d[1] = to_tf32(pb[j].y);
            d[2] = to_tf32(pb[j].z); d[3] = to_tf32(pb[j].w);
        }
        __syncthreads();

        if (it + 1 < niter) {
            const float* An = Ab + (it + 1) * 32;
            const float* Bn = Bb + (it + 1) * 32;
            #pragma unroll
            for (int j = 0; j < 4; j++) pa[j] = *(const float4*)(An + (long)32 * j * lda);
            #pragma unroll
            for (int j = 0; j < 8; j++) pb[j] = *(const float4*)(Bn + (long)32 * j * ldb);
        }

        #pragma unroll
        for (int kk = 0; kk < 32; kk += 8) {
            unsigned af[4][4], bf[8][2];
            #pragma unroll
            for (int mt = 0; mt < 4; mt++) {
                const int r = wm + mt * 16 + g;
                af[mt][0] = fu(As[r * GP + kk + qd]);
                af[mt][1] = fu(As[(r + 8) * GP + kk + qd]);
                af[mt][2] = fu(As[r * GP + kk + qd + 4]);
                af[mt][3] = fu(As[(r + 8) * GP + kk + qd + 4]);
            }
            #pragma unroll
            for (int nt = 0; nt < 8; nt++) {
                const int rb = wn + nt * 8 + g;
                bf[nt][0] = fu(Bs[rb * GP + kk + qd]);
                bf[nt][1] = fu(Bs[rb * GP + kk + qd + 4]);
            }
            #pragma unroll
            for (int mt = 0; mt < 4; mt++)
                #pragma unroll
                for (int nt = 0; nt < 8; nt++)
                    mma_tf32(acc[mt][nt], af[mt], bf[nt]);
        }
    }

    #pragma unroll
    for (int mt = 0; mt < 4; mt++) {
        const int r0 = bm + wm + mt * 16 + g;
        #pragma unroll
        for (int nt = 0; nt < 8; nt++) {
            const int cc = bn + wn + nt * 8 + 2 * qd;
            float2 lo = make_float2(acc[mt][nt][0], acc[mt][nt][1]);
            float2 hi = make_float2(acc[mt][nt][2], acc[mt][nt][3]);
            *(float2*)&C[(long)r0 * ldc + cc]       = lo;
            *(float2*)&C[(long)(r0 + 8) * ldc + cc] = hi;
        }
    }
}

// ===========================================================================
// RoPE (in-place): tmp = concat(x[64:], x[:64]), NO negation.
// ===========================================================================
__global__ __launch_bounds__(256)
void rope_kernel(const float* __restrict__ cosb, const float* __restrict__ sinb)
{
    const int s = blockIdx.x;
    const float* cs = cosb + s * 128;
    const float* sn = sinb + s * 128;
    float* row = g_qkv + (long)s * QKV_LD;
    for (int p = threadIdx.x; p < 20 * 64; p += 256) {
        const int head = p >> 6;
        const int d = p & 63;
        float* base = row + head * 128;
        float x0 = base[d];
        float x1 = base[d + 64];
        base[d]      = x0 * cs[d]      + x1 * sn[d];
        base[d + 64] = x1 * cs[d + 64] + x0 * sn[d + 64];
    }
}

// ===========================================================================
// Sliding-window flash attention, tf32 mma.
// grid (16 heads, 32 q-blocks of 128), 256 threads = 8 warps.
// Each warp owns a 16-row strip (full 64-col width for S).
// ===========================================================================
#define QP 132
#define KP 132
#define VP 136
#define PP 68
#define ATTN_SMEM ((128 * QP + 64 * KP + 64 * VP + 128 * PP) * 4)

__global__ __launch_bounds__(256, 1)
void attn_tf32()
{
    extern __shared__ float sm[];
    float* Qs = sm;                 // [128][QP]
    float* Ks = Qs + 128 * QP;      // [64][KP]
    float* Vs = Ks + 64 * KP;       // [64][VP]   (row = key, col = dim)
    float* Ps = Vs + 64 * VP;       // [128][PP]

    const int h  = blockIdx.x;
    const int q0 = (int)(gridDim.y - 1 - blockIdx.y) * 128;  // heavy blocks first
    const int kvh = h >> 2;
    const int tid = threadIdx.x;
    const int w = tid >> 5, lane = tid & 31;
    const int g = lane >> 2, qd = lane & 3;
    const int wm = w * 16;

    // Q tile (scaled, tf32)
    for (int idx = tid; idx < 128 * 32; idx += 256) {
        int r = idx >> 5, c = (idx & 31) * 4;
        float4 v = *(const float4*)(g_qkv + (long)(q0 + r) * QKV_LD + h * 128 + c);
        float* q = Qs + r * QP + c;
        q[0] = to_tf32(v.x * SCALE_F); q[1] = to_tf32(v.y * SCALE_F);
        q[2] = to_tf32(v.z * SCALE_F); q[3] = to_tf32(v.w * SCALE_F);
    }

    float o[16][4];
    #pragma unroll
    for (int nt = 0; nt < 16; nt++)
        #pragma unroll
        for (int e = 0; e < 4; e++) o[nt][e] = 0.f;
    float m0 = -1e30f, m1 = -1e30f, l0 = 0.f, l1 = 0.f;

    const int kstart = (q0 >= WIN_) ? q0 - WIN_ : 0;
    const int kend   = q0 + 64;

    for (int k0 = kstart; k0 <= kend; k0 += 64) {
        __syncthreads();   // previous iteration done reading Ks/Vs/Ps
        for (int idx = tid; idx < 64 * 32; idx += 256) {
            int r = idx >> 5, c = (idx & 31) * 4;
            const float* src = g_qkv + (long)(k0 + r) * QKV_LD + 2048 + kvh * 128 + c;
            float4 kv = *(const float4*)src;
            float4 vv = *(const float4*)(src + 512);
            float* kd = Ks + r * KP + c;
            kd[0] = to_tf32(kv.x); kd[1] = to_tf32(kv.y);
            kd[2] = to_tf32(kv.z); kd[3] = to_tf32(kv.w);
            float* vd = Vs + r * VP + c;
            vd[0] = to_tf32(vv.x); vd[1] = to_tf32(vv.y);
            vd[2] = to_tf32(vv.z); vd[3] = to_tf32(vv.w);
        }
        __syncthreads();

        // ---- S = Q * K^T  (warp strip: 16 x 64) ----
        float s[8][4];
        #pragma unroll
        for (int nt = 0; nt < 8; nt++)
            #pragma unroll
            for (int e = 0; e < 4; e++) s[nt][e] = 0.f;

        #pragma unroll
        for (int kk = 0; kk < 128; kk += 8) {
            unsigned af[4];
            af[0] = fu(Qs[(wm + g) * QP + kk + qd]);
            af[1] = fu(Qs[(wm + g + 8) * QP + kk + qd]);
            af[2] = fu(Qs[(wm + g) * QP + kk + qd + 4]);
            af[3] = fu(Qs[(wm + g + 8) * QP + kk + qd + 4]);
            #pragma unroll
            for (int nt = 0; nt < 8; nt++) {
                unsigned bf[2];
                bf[0] = fu(Ks[(nt * 8 + g) * KP + kk + qd]);
                bf[1] = fu(Ks[(nt * 8 + g) * KP + kk + qd + 4]);
                mma_tf32(s[nt], af, bf);
            }
        }

        // ---- mask + online softmax (rows r0 = wm+g, r1 = r0+8) ----
        const int r0 = q0 + wm + g, r1 = r0 + 8;
        float mx0 = -1e30f, mx1 = -1e30f;
        #pragma unroll
        for (int nt = 0; nt < 8; nt++) {
            const int j0 = k0 + nt * 8 + 2 * qd;
            const int j1 = j0 + 1;
            if (!(j0 <= r0 && (r0 - j0) < WIN_)) s[nt][0] = -1e30f;
            if (!(j1 <= r0 && (r0 - j1) < WIN_)) s[nt][1] = -1e30f;
            if (!(j0 <= r1 && (r1 - j0) < WIN_)) s[nt][2] = -1e30f;
            if (!(j1 <= r1 && (r1 - j1) < WIN_)) s[nt][3] = -1e30f;
            mx0 = fmaxf(mx0, fmaxf(s[nt][0], s[nt][1]));
            mx1 = fmaxf(mx1, fmaxf(s[nt][2], s[nt][3]));
        }
        mx0 = fmaxf(mx0, __shfl_xor_sync(0xffffffffu, mx0, 1));
        mx0 = fmaxf(mx0, __shfl_xor_sync(0xffffffffu, mx0, 2));
        mx1 = fmaxf(mx1, __shfl_xor_sync(0xffffffffu, mx1, 1));
        mx1 = fmaxf(mx1, __shfl_xor_sync(0xffffffffu, mx1, 2));

        const float mn0 = fmaxf(m0, mx0), mn1 = fmaxf(m1, mx1);
        const float sc0 = __expf(m0 - mn0), sc1 = __expf(m1 - mn1);
        float rs0 = 0.f, rs1 = 0.f;
        #pragma unroll
        for (int nt = 0; nt < 8; nt++) {
            float p0 = __expf(s[nt][0] - mn0);
            float p1 = __expf(s[nt][1] - mn0);
            float p2 = __expf(s[nt][2] - mn1);
            float p3 = __expf(s[nt][3] - mn1);
            rs0 += p0 + p1; rs1 += p2 + p3;
            *(float2*)&Ps[(wm + g) * PP + nt * 8 + 2 * qd] =
                make_float2(to_tf32(p0), to_tf32(p1));
            *(float2*)&Ps[(wm + g + 8) * PP + nt * 8 + 2 * qd] =
                make_float2(to_tf32(p2), to_tf32(p3));
        }
        rs0 += __shfl_xor_sync(0xffffffffu, rs0, 1);
        rs0 += __shfl_xor_sync(0xffffffffu, rs0, 2);
        rs1 += __shfl_xor_sync(0xffffffffu, rs1, 1);
        rs1 += __shfl_xor_sync(0xffffffffu, rs1, 2);

        l0 = l0 * sc0 + rs0; l1 = l1 * sc1 + rs1;
        m0 = mn0; m1 = mn1;
        #pragma unroll
        for (int nt = 0; nt < 16; nt++) {
            o[nt][0] *= sc0; o[nt][1] *= sc0;
            o[nt][2] *= sc1; o[nt][3] *= sc1;
        }
        __syncthreads();   // Ps visible to whole warp's fragment loads

        // ---- O += P * V  (warp strip: 16 x 128) ----
        #pragma unroll
        for (int kk = 0; kk < 64; kk += 8) {
            unsigned pa[4];
            pa[0] = fu(Ps[(wm + g) * PP + kk + qd]);
            pa[1] = fu(Ps[(wm + g + 8) * PP + kk + qd]);
            pa[2] = fu(Ps[(wm + g) * PP + kk + qd + 4]);
            pa[3] = fu(Ps[(wm + g + 8) * PP + kk + qd + 4]);
            #pragma unroll
            for (int nt = 0; nt < 16; nt++) {
                unsigned bf[2];
                bf[0] = fu(Vs[(kk + qd) * VP + nt * 8 + g]);
                bf[1] = fu(Vs[(kk + qd + 4) * VP + nt * 8 + g]);
                mma_tf32(o[nt], pa, bf);
            }
        }
    }

    // ---- epilogue: normalize, write [s, h*128 + d] ----
    const float i0 = 1.f / l0, i1 = 1.f / l1;
    const int rr0 = q0 + wm + g;
    #pragma unroll
    for (int nt = 0; nt < 16; nt++) {
        const int cc = h * 128 + nt * 8 + 2 * qd;
        *(float2*)&g_attn[(long)rr0 * HID + cc] =
            make_float2(o[nt][0] * i0, o[nt][1] * i0);
        *(float2*)&g_attn[(long)(rr0 + 8) * HID + cc] =
            make_float2(o[nt][2] * i1, o[nt][3] * i1);
    }
}

// ===========================================================================
// Launch
// ===========================================================================
#define GEMM_SMEM ((128 + 256) * GP * 4)

extern "C" void kernel_launch(void* const* d_in, const int* in_sizes, int n_in,
                              void* d_out, int out_size)
{
    (void)in_sizes; (void)n_in; (void)out_size;
    const float* hidden = (const float*)d_in[0];
    const float* wq = (const float*)d_in[1];
    const float* wk = (const float*)d_in[2];
    const float* wv = (const float*)d_in[3];
    const float* wo = (const float*)d_in[4];
    const float* cosb = (const float*)d_in[5];
    const float* sinb = (const float*)d_in[6];
    float* out = (float*)d_out;

    void *qkvp, *attnp;
    cudaGetSymbolAddress(&qkvp, g_qkv);
    cudaGetSymbolAddress(&attnp, g_attn);
    float* qkv  = (float*)qkvp;
    float* attn = (float*)attnp;

    static int attrs_set = 0;
    if (!attrs_set) {
        cudaFuncSetAttribute(gemm_tf32, cudaFuncAttributeMaxDynamicSharedMemorySize, GEMM_SMEM);
        cudaFuncSetAttribute(attn_tf32, cudaFuncAttributeMaxDynamicSharedMemorySize, ATTN_SMEM);
        attrs_set = 1;
    }

    // QKV projections (C = A * W^T)
    gemm_tf32<<<dim3(8, 32), 256, GEMM_SMEM>>>(hidden, HID, wq, HID, qkv,        QKV_LD, HID);
    gemm_tf32<<<dim3(2, 32), 256, GEMM_SMEM>>>(hidden, HID, wk, HID, qkv + 2048, QKV_LD, HID);
    gemm_tf32<<<dim3(2, 32), 256, GEMM_SMEM>>>(hidden, HID, wv, HID, qkv + 2560, QKV_LD, HID);

    // RoPE on q and k
    rope_kernel<<<S_LEN, 256>>>(cosb, sinb);

    // sliding-window attention (tf32 tensor cores)
    attn_tf32<<<dim3(16, 32), 256, ATTN_SMEM>>>();

    // output projection
    gemm_tf32<<<dim3(8, 32), 256, GEMM_SMEM>>>(attn, HID, wo, HID, out, HID, HID);
}

// round 7
// speedup vs baseline: 3.4943x; 1.1031x over previous
#include <cuda_runtime.h>
#include <cstdint>

#define S_LEN 4096
#define HID   2048
#define QKV_LD 3072
#define WIN_  1024
#define SCALE_F 0.08838834764831845f   // 128^-0.5

static __device__ float g_qkv [S_LEN * QKV_LD];   // [s][ q(16*128) | k(4*128) | v(4*128) ]
static __device__ float g_attn[S_LEN * HID];

// ---------------------------------------------------------------------------
// helpers
// ---------------------------------------------------------------------------
__device__ __forceinline__ float to_tf32(float x) {
    unsigned u;
    asm("cvt.rna.tf32.f32 %0, %1;" : "=r"(u) : "f"(x));
    return __uint_as_float(u);
}
__device__ __forceinline__ unsigned cvu(float x) {
    unsigned u;
    asm("cvt.rna.tf32.f32 %0, %1;" : "=r"(u) : "f"(x));
    return u;
}
__device__ __forceinline__ unsigned fu(float x) { return __float_as_uint(x); }

__device__ __forceinline__ uint32_t smem_u32(const void* p) {
    uint32_t a;
    asm("{ .reg .u64 t; cvta.to.shared.u64 t, %1; cvt.u32.u64 %0, t; }"
        : "=r"(a) : "l"(p));
    return a;
}

#define CP_ASYNC16(saddr, gptr) \
    asm volatile("cp.async.cg.shared.global [%0], [%1], 16;" \
        :: "r"((uint32_t)(saddr)), "l"(gptr) : "memory")
#define CP_COMMIT() asm volatile("cp.async.commit_group;" ::: "memory")
#define CP_WAIT(n)  asm volatile("cp.async.wait_group %0;" :: "n"(n) : "memory")

// D(16x8) += A(16x8) * B(8x8)^T, tf32
__device__ __forceinline__ void mma_tf32(float* c, const unsigned* a, const unsigned* b) {
    asm volatile(
        "mma.sync.aligned.m16n8k8.row.col.f32.tf32.tf32.f32 "
        "{%0,%1,%2,%3}, {%4,%5,%6,%7}, {%8,%9}, {%0,%1,%2,%3};\n"
        : "+f"(c[0]), "+f"(c[1]), "+f"(c[2]), "+f"(c[3])
        : "r"(a[0]), "r"(a[1]), "r"(a[2]), "r"(a[3]), "r"(b[0]), "r"(b[1]));
}

// ===========================================================================
// GEMM:  C[:, cout..] = A[M,K] * B[256 rows, K]^T   (row-major, K contiguous)
// BM=128, BN=256, BK=32; 256 threads = 8 warps (2M x 4N), warp tile 64x64.
// 3-stage cp.async pipeline; cvt.rna on fragments post-LDS.
// Per-block weight select: blocks [0,nb0) -> B0, [nb0,nb0+nb1) -> B1, rest B2
// (fuses Q/K/V projections into one launch).
// ===========================================================================
#define STG   3
#define GP    36                        // smem row pitch in floats (144 B)
#define ROWB  (GP * 4)
#define A_BYT (128 * ROWB)
#define B_BYT (256 * ROWB)
#define STBYT (A_BYT + B_BYT)           // 55296 B / stage
#define GEMM_SMEM (STG * STBYT)         // 162 KB

__global__ __launch_bounds__(256, 1)
void gemm_cp(const float* __restrict__ A, int lda,
             const float* __restrict__ B0, const float* __restrict__ B1,
             const float* __restrict__ B2, int ldb,
             float* __restrict__ C, int ldc, int K, int nb0, int nb1)
{
    extern __shared__ char sm[];
    const uint32_t sb = smem_u32(sm);
    const int tid = threadIdx.x;
    const int w = tid >> 5, lane = tid & 31;
    const int g = lane >> 2, qd = lane & 3;
    const int wm = (w & 1) * 64;
    const int wn = (w >> 1) * 64;
    const int bm = blockIdx.y * 128;

    const int bx = blockIdx.x;
    const float* B;
    int cout;
    if (bx < nb0)            { B = B0 + (long)(bx * 256) * ldb;              cout = bx * 256; }
    else if (bx < nb0 + nb1) { B = B1 + (long)((bx - nb0) * 256) * ldb;      cout = nb0 * 256 + (bx - nb0) * 256; }
    else                     { B = B2 + (long)((bx - nb0 - nb1) * 256) * ldb; cout = (nb0 + nb1) * 256 + (bx - nb0 - nb1) * 256; }

    float acc[4][8][4];
    #pragma unroll
    for (int mt = 0; mt < 4; mt++)
        #pragma unroll
        for (int nt = 0; nt < 8; nt++)
            #pragma unroll
            for (int e = 0; e < 4; e++) acc[mt][nt][e] = 0.f;

    const int lr = tid >> 3;           // row within 32-row group
    const int lc = tid & 7;            // 16B chunk within row

    const int niter = K / 32;

    // ---- prologue: stages 0..STG-2 ----
    #pragma unroll
    for (int s = 0; s < STG - 1; s++) {
        const int kk = s * 32;
        const uint32_t ab = sb + s * STBYT;
        const uint32_t bb = ab + A_BYT;
        #pragma unroll
        for (int i = 0; i < 4; i++) {
            const int r = lr + 32 * i;
            CP_ASYNC16(ab + r * ROWB + lc * 16, A + (long)(bm + r) * lda + kk + lc * 4);
        }
        #pragma unroll
        for (int i = 0; i < 8; i++) {
            const int r = lr + 32 * i;
            CP_ASYNC16(bb + r * ROWB + lc * 16, B + (long)r * ldb + kk + lc * 4);
        }
        CP_COMMIT();
    }

    for (int it = 0; it < niter; it++) {
        CP_WAIT(STG - 2);
        __syncthreads();

        // prefetch stage it+STG-1 into buffer (it+STG-1)%STG (== (it-1)%STG, safe post-sync)
        const int nxt = it + STG - 1;
        if (nxt < niter) {
            const int s = nxt % STG;
            const int kk = nxt * 32;
            const uint32_t ab = sb + s * STBYT;
            const uint32_t bb = ab + A_BYT;
            #pragma unroll
            for (int i = 0; i < 4; i++) {
                const int r = lr + 32 * i;
                CP_ASYNC16(ab + r * ROWB + lc * 16, A + (long)(bm + r) * lda + kk + lc * 4);
            }
            #pragma unroll
            for (int i = 0; i < 8; i++) {
                const int r = lr + 32 * i;
                CP_ASYNC16(bb + r * ROWB + lc * 16, B + (long)r * ldb + kk + lc * 4);
            }
        }
        CP_COMMIT();   // commit every iter so wait_group counting stays uniform

        const float* As = (const float*)(sm + (it % STG) * STBYT);
        const float* Bs = (const float*)(sm + (it % STG) * STBYT + A_BYT);

        #pragma unroll
        for (int kk = 0; kk < 32; kk += 8) {
            unsigned af[4][4], bf[8][2];
            #pragma unroll
            for (int mt = 0; mt < 4; mt++) {
                const int r = wm + mt * 16 + g;
                af[mt][0] = cvu(As[r * GP + kk + qd]);
                af[mt][1] = cvu(As[(r + 8) * GP + kk + qd]);
                af[mt][2] = cvu(As[r * GP + kk + qd + 4]);
                af[mt][3] = cvu(As[(r + 8) * GP + kk + qd + 4]);
            }
            #pragma unroll
            for (int nt = 0; nt < 8; nt++) {
                const int rb = wn + nt * 8 + g;
                bf[nt][0] = cvu(Bs[rb * GP + kk + qd]);
                bf[nt][1] = cvu(Bs[rb * GP + kk + qd + 4]);
            }
            #pragma unroll
            for (int mt = 0; mt < 4; mt++)
                #pragma unroll
                for (int nt = 0; nt < 8; nt++)
                    mma_tf32(acc[mt][nt], af[mt], bf[nt]);
        }
    }

    #pragma unroll
    for (int mt = 0; mt < 4; mt++) {
        const int r0 = bm + wm + mt * 16 + g;
        #pragma unroll
        for (int nt = 0; nt < 8; nt++) {
            const int cc = cout + wn + nt * 8 + 2 * qd;
            *(float2*)&C[(long)r0 * ldc + cc] =
                make_float2(acc[mt][nt][0], acc[mt][nt][1]);
            *(float2*)&C[(long)(r0 + 8) * ldc + cc] =
                make_float2(acc[mt][nt][2], acc[mt][nt][3]);
        }
    }
}

// ===========================================================================
// RoPE (in-place): tmp = concat(x[64:], x[:64]), NO negation.
// ===========================================================================
__global__ __launch_bounds__(256)
void rope_kernel(const float* __restrict__ cosb, const float* __restrict__ sinb)
{
    const int s = blockIdx.x;
    const float* cs = cosb + s * 128;
    const float* sn = sinb + s * 128;
    float* row = g_qkv + (long)s * QKV_LD;
    for (int p = threadIdx.x; p < 20 * 64; p += 256) {
        const int head = p >> 6;
        const int d = p & 63;
        float* base = row + head * 128;
        float x0 = base[d];
        float x1 = base[d + 64];
        base[d]      = x0 * cs[d]      + x1 * sn[d];
        base[d + 64] = x1 * cs[d + 64] + x0 * sn[d + 64];
    }
}

// ===========================================================================
// Sliding-window flash attention, tf32 mma.sync (proven R4 path, unchanged).
// grid (16 heads, 32 q-blocks of 128), 256 threads = 8 warps.
// ===========================================================================
#define QP 132
#define KP 132
#define VP 136
#define PP 68
#define ATTN_SMEM ((128 * QP + 64 * KP + 64 * VP + 128 * PP) * 4)

__global__ __launch_bounds__(256, 1)
void attn_tf32()
{
    extern __shared__ float smf[];
    float* Qs = smf;                // [128][QP]
    float* Ks = Qs + 128 * QP;      // [64][KP]
    float* Vs = Ks + 64 * KP;       // [64][VP]
    float* Ps = Vs + 64 * VP;       // [128][PP]

    const int h  = blockIdx.x;
    const int q0 = (int)(gridDim.y - 1 - blockIdx.y) * 128;
    const int kvh = h >> 2;
    const int tid = threadIdx.x;
    const int w = tid >> 5, lane = tid & 31;
    const int g = lane >> 2, qd = lane & 3;
    const int wm = w * 16;

    for (int idx = tid; idx < 128 * 32; idx += 256) {
        int r = idx >> 5, c = (idx & 31) * 4;
        float4 v = *(const float4*)(g_qkv + (long)(q0 + r) * QKV_LD + h * 128 + c);
        float* q = Qs + r * QP + c;
        q[0] = to_tf32(v.x * SCALE_F); q[1] = to_tf32(v.y * SCALE_F);
        q[2] = to_tf32(v.z * SCALE_F); q[3] = to_tf32(v.w * SCALE_F);
    }

    float o[16][4];
    #pragma unroll
    for (int nt = 0; nt < 16; nt++)
        #pragma unroll
        for (int e = 0; e < 4; e++) o[nt][e] = 0.f;
    float m0 = -1e30f, m1 = -1e30f, l0 = 0.f, l1 = 0.f;

    const int kstart = (q0 >= WIN_) ? q0 - WIN_ : 0;
    const int kend   = q0 + 64;

    for (int k0 = kstart; k0 <= kend; k0 += 64) {
        __syncthreads();
        for (int idx = tid; idx < 64 * 32; idx += 256) {
            int r = idx >> 5, c = (idx & 31) * 4;
            const float* src = g_qkv + (long)(k0 + r) * QKV_LD + 2048 + kvh * 128 + c;
            float4 kv = *(const float4*)src;
            float4 vv = *(const float4*)(src + 512);
            float* kd = Ks + r * KP + c;
            kd[0] = to_tf32(kv.x); kd[1] = to_tf32(kv.y);
            kd[2] = to_tf32(kv.z); kd[3] = to_tf32(kv.w);
            float* vd = Vs + r * VP + c;
            vd[0] = to_tf32(vv.x); vd[1] = to_tf32(vv.y);
            vd[2] = to_tf32(vv.z); vd[3] = to_tf32(vv.w);
        }
        __syncthreads();

        float s[8][4];
        #pragma unroll
        for (int nt = 0; nt < 8; nt++)
            #pragma unroll
            for (int e = 0; e < 4; e++) s[nt][e] = 0.f;

        #pragma unroll
        for (int kk = 0; kk < 128; kk += 8) {
            unsigned af[4];
            af[0] = fu(Qs[(wm + g) * QP + kk + qd]);
            af[1] = fu(Qs[(wm + g + 8) * QP + kk + qd]);
            af[2] = fu(Qs[(wm + g) * QP + kk + qd + 4]);
            af[3] = fu(Qs[(wm + g + 8) * QP + kk + qd + 4]);
            #pragma unroll
            for (int nt = 0; nt < 8; nt++) {
                unsigned bf[2];
                bf[0] = fu(Ks[(nt * 8 + g) * KP + kk + qd]);
                bf[1] = fu(Ks[(nt * 8 + g) * KP + kk + qd + 4]);
                mma_tf32(s[nt], af, bf);
            }
        }

        const int r0 = q0 + wm + g, r1 = r0 + 8;
        float mx0 = -1e30f, mx1 = -1e30f;
        #pragma unroll
        for (int nt = 0; nt < 8; nt++) {
            const int j0 = k0 + nt * 8 + 2 * qd;
            const int j1 = j0 + 1;
            if (!(j0 <= r0 && (r0 - j0) < WIN_)) s[nt][0] = -1e30f;
            if (!(j1 <= r0 && (r0 - j1) < WIN_)) s[nt][1] = -1e30f;
            if (!(j0 <= r1 && (r1 - j0) < WIN_)) s[nt][2] = -1e30f;
            if (!(j1 <= r1 && (r1 - j1) < WIN_)) s[nt][3] = -1e30f;
            mx0 = fmaxf(mx0, fmaxf(s[nt][0], s[nt][1]));
            mx1 = fmaxf(mx1, fmaxf(s[nt][2], s[nt][3]));
        }
        mx0 = fmaxf(mx0, __shfl_xor_sync(0xffffffffu, mx0, 1));
        mx0 = fmaxf(mx0, __shfl_xor_sync(0xffffffffu, mx0, 2));
        mx1 = fmaxf(mx1, __shfl_xor_sync(0xffffffffu, mx1, 1));
        mx1 = fmaxf(mx1, __shfl_xor_sync(0xffffffffu, mx1, 2));

        const float mn0 = fmaxf(m0, mx0), mn1 = fmaxf(m1, mx1);
        const float sc0 = __expf(m0 - mn0), sc1 = __expf(m1 - mn1);
        float rs0 = 0.f, rs1 = 0.f;
        #pragma unroll
        for (int nt = 0; nt < 8; nt++) {
            float p0 = __expf(s[nt][0] - mn0);
            float p1 = __expf(s[nt][1] - mn0);
            float p2 = __expf(s[nt][2] - mn1);
            float p3 = __expf(s[nt][3] - mn1);
            rs0 += p0 + p1; rs1 += p2 + p3;
            *(float2*)&Ps[(wm + g) * PP + nt * 8 + 2 * qd] =
                make_float2(to_tf32(p0), to_tf32(p1));
            *(float2*)&Ps[(wm + g + 8) * PP + nt * 8 + 2 * qd] =
                make_float2(to_tf32(p2), to_tf32(p3));
        }
        rs0 += __shfl_xor_sync(0xffffffffu, rs0, 1);
        rs0 += __shfl_xor_sync(0xffffffffu, rs0, 2);
        rs1 += __shfl_xor_sync(0xffffffffu, rs1, 1);
        rs1 += __shfl_xor_sync(0xffffffffu, rs1, 2);

        l0 = l0 * sc0 + rs0; l1 = l1 * sc1 + rs1;
        m0 = mn0; m1 = mn1;
        #pragma unroll
        for (int nt = 0; nt < 16; nt++) {
            o[nt][0] *= sc0; o[nt][1] *= sc0;
            o[nt][2] *= sc1; o[nt][3] *= sc1;
        }
        __syncthreads();

        #pragma unroll
        for (int kk = 0; kk < 64; kk += 8) {
            unsigned pa[4];
            pa[0] = fu(Ps[(wm + g) * PP + kk + qd]);
            pa[1] = fu(Ps[(wm + g + 8) * PP + kk + qd]);
            pa[2] = fu(Ps[(wm + g) * PP + kk + qd + 4]);
            pa[3] = fu(Ps[(wm + g + 8) * PP + kk + qd + 4]);
            #pragma unroll
            for (int nt = 0; nt < 16; nt++) {
                unsigned bf[2];
                bf[0] = fu(Vs[(kk + qd) * VP + nt * 8 + g]);
                bf[1] = fu(Vs[(kk + qd + 4) * VP + nt * 8 + g]);
                mma_tf32(o[nt], pa, bf);
            }
        }
    }

    const float i0 = 1.f / l0, i1 = 1.f / l1;
    const int rr0 = q0 + wm + g;
    #pragma unroll
    for (int nt = 0; nt < 16; nt++) {
        const int cc = h * 128 + nt * 8 + 2 * qd;
        *(float2*)&g_attn[(long)rr0 * HID + cc] =
            make_float2(o[nt][0] * i0, o[nt][1] * i0);
        *(float2*)&g_attn[(long)(rr0 + 8) * HID + cc] =
            make_float2(o[nt][2] * i1, o[nt][3] * i1);
    }
}

// ===========================================================================
// Launch
// ===========================================================================
extern "C" void kernel_launch(void* const* d_in, const int* in_sizes, int n_in,
                              void* d_out, int out_size)
{
    (void)in_sizes; (void)n_in; (void)out_size;
    const float* hidden = (const float*)d_in[0];
    const float* wq = (const float*)d_in[1];
    const float* wk = (const float*)d_in[2];
    const float* wv = (const float*)d_in[3];
    const float* wo = (const float*)d_in[4];
    const float* cosb = (const float*)d_in[5];
    const float* sinb = (const float*)d_in[6];
    float* out = (float*)d_out;

    void *qkvp, *attnp;
    cudaGetSymbolAddress(&qkvp, g_qkv);
    cudaGetSymbolAddress(&attnp, g_attn);
    float* qkv  = (float*)qkvp;
    float* attn = (float*)attnp;

    static int attrs_set = 0;
    if (!attrs_set) {
        cudaFuncSetAttribute(gemm_cp,   cudaFuncAttributeMaxDynamicSharedMemorySize, GEMM_SMEM);
        cudaFuncSetAttribute(attn_tf32, cudaFuncAttributeMaxDynamicSharedMemorySize, ATTN_SMEM);
        attrs_set = 1;
    }

    // fused QKV projection: one launch, per-block weight select
    gemm_cp<<<dim3(12, 32), 256, GEMM_SMEM>>>(hidden, HID, wq, wk, wv, HID,
                                              qkv, QKV_LD, HID, 8, 2);

    // RoPE on q and k
    rope_kernel<<<S_LEN, 256>>>(cosb, sinb);

    // sliding-window attention (mma.sync tf32)
    attn_tf32<<<dim3(16, 32), 256, ATTN_SMEM>>>();

    // output projection
    gemm_cp<<<dim3(8, 32), 256, GEMM_SMEM>>>(attn, HID, wo, wo, wo, HID,
                                             out, HID, HID, 8, 0);
}